// round 14
// baseline (speedup 1.0000x reference)
#include <cuda_runtime.h>
#include <cuda_fp16.h>
#include <mma.h>
#include <math.h>
#include <stdint.h>

using namespace nvcuda;

#define NN 100000
#define EE 1600000
#define NEG 0.01f
#define COLCAP 2000000   // EE + 3*NN padding worst case, rounded up

// ---------------- scratch (device globals) ---------------------------------
__device__ __half2 g_h[(NN + 1) * 32];   // row NN stays zero forever (pad target)
__device__ __half2 g_bufA[NN * 32];
__device__ __half2 g_bufB[NN * 32];
__device__ int   g_cnt[NN];
__device__ int2  g_rowcnt[NN];           // {rowptr, cnt} packed, one LDG.64
__device__ int   g_rowptr[NN];
__device__ int   g_pos[NN];
__device__ int   g_col[COLCAP];
__device__ float g_dinv[NN];
__device__ int   g_bsum[128];

// ---------------- CSR build ------------------------------------------------
__global__ void k_zero_cnt() {
    int i = blockIdx.x * blockDim.x + threadIdx.x;
    if (i < NN) g_cnt[i] = 0;
}

__global__ void k_hist(const int* __restrict__ dst) {
    cudaGridDependencySynchronize();
    int t = blockIdx.x * blockDim.x + threadIdx.x;
    if (t * 8 < EE) {
        int4 d0 = ((const int4*)dst)[t * 2];
        int4 d1 = ((const int4*)dst)[t * 2 + 1];
        atomicAdd(&g_cnt[d0.x], 1);
        atomicAdd(&g_cnt[d0.y], 1);
        atomicAdd(&g_cnt[d0.z], 1);
        atomicAdd(&g_cnt[d0.w], 1);
        atomicAdd(&g_cnt[d1.x], 1);
        atomicAdd(&g_cnt[d1.y], 1);
        atomicAdd(&g_cnt[d1.z], 1);
        atomicAdd(&g_cnt[d1.w], 1);
    }
}

__global__ void k_scanA() {
    __shared__ int s[1024];
    cudaGridDependencySynchronize();
    int tid = threadIdx.x;
    int i = blockIdx.x * 1024 + tid;
    int v = (i < NN) ? g_cnt[i] : 0;
    if (i < NN) g_dinv[i] = rsqrtf((float)(v + 1));
    int vp = (v + 3) & ~3;               // padded count
    s[tid] = vp;
    __syncthreads();
    #pragma unroll
    for (int off = 1; off < 1024; off <<= 1) {
        int t = (tid >= off) ? s[tid - off] : 0;
        __syncthreads();
        s[tid] += t;
        __syncthreads();
    }
    if (i < NN) g_rowptr[i] = s[tid] - vp;
    if (tid == 1023) g_bsum[blockIdx.x] = s[1023];
}

__global__ void k_scanB(int nb) {
    cudaGridDependencySynchronize();
    int lane = threadIdx.x;
    int base = lane * 4;
    int v0 = (base + 0 < nb) ? g_bsum[base + 0] : 0;
    int v1 = (base + 1 < nb) ? g_bsum[base + 1] : 0;
    int v2 = (base + 2 < nb) ? g_bsum[base + 2] : 0;
    int v3 = (base + 3 < nb) ? g_bsum[base + 3] : 0;
    int s1 = v0 + v1, s2 = s1 + v2, s3 = s2 + v3;
    int tot = s3;
    int run = tot;
    #pragma unroll
    for (int off = 1; off < 32; off <<= 1) {
        int t = __shfl_up_sync(0xffffffffu, run, off);
        if (lane >= off) run += t;
    }
    int excl = run - tot;
    if (base + 0 < nb) g_bsum[base + 0] = excl;
    if (base + 1 < nb) g_bsum[base + 1] = excl + v0;
    if (base + 2 < nb) g_bsum[base + 2] = excl + s1;
    if (base + 3 < nb) g_bsum[base + 3] = excl + s2;
}

__global__ void k_scanC() {
    cudaGridDependencySynchronize();
    int i = blockIdx.x * blockDim.x + threadIdx.x;
    if (i < NN) {
        int rp = g_rowptr[i] + g_bsum[i >> 10];
        int cnt = g_cnt[i];
        g_rowcnt[i] = make_int2(rp, cnt);
        g_pos[i] = rp;
        int pad = (cnt + 3) & ~3;
        for (int k = cnt; k < pad; k++) g_col[rp + k] = NN;  // dummy -> zero row
    }
}

__global__ void k_scatter(const int* __restrict__ src, const int* __restrict__ dst) {
    cudaGridDependencySynchronize();
    int t = blockIdx.x * blockDim.x + threadIdx.x;
    if (t * 8 < EE) {
        int4 d0 = ((const int4*)dst)[t * 2];
        int4 d1 = ((const int4*)dst)[t * 2 + 1];
        int4 s0 = ((const int4*)src)[t * 2];
        int4 s1 = ((const int4*)src)[t * 2 + 1];
        int p0 = atomicAdd(&g_pos[d0.x], 1);
        int p1 = atomicAdd(&g_pos[d0.y], 1);
        int p2 = atomicAdd(&g_pos[d0.z], 1);
        int p3 = atomicAdd(&g_pos[d0.w], 1);
        int p4 = atomicAdd(&g_pos[d1.x], 1);
        int p5 = atomicAdd(&g_pos[d1.y], 1);
        int p6 = atomicAdd(&g_pos[d1.z], 1);
        int p7 = atomicAdd(&g_pos[d1.w], 1);
        g_col[p0] = s0.x;
        g_col[p1] = s0.y;
        g_col[p2] = s0.z;
        g_col[p3] = s0.w;
        g_col[p4] = s1.x;
        g_col[p5] = s1.y;
        g_col[p6] = s1.z;
        g_col[p7] = s1.w;
    }
}

// ---------------- WMMA GEMM: h'[N,64](fp16) = dinv[row]*(in @ W) -----------
template<bool F32IN>
__global__ void __launch_bounds__(256) k_gemm_wmma(
    const void* __restrict__ inv, const float* __restrict__ W,
    __half2* __restrict__ out) {
    __shared__ __align__(16) char sraw[24576];
    half* As = (half*)sraw;             // 128 x 64 (ldm 64)
    half* Bs = (half*)(sraw + 16384);   // 64 x 64  (ldm 64)
    int tid  = threadIdx.x;
    int warp = tid >> 5, lane = tid & 31;
    int rowbase = blockIdx.x * 128;

    #pragma unroll
    for (int k = 0; k < 4; k++) {
        int i = tid + k * 256;
        float4 w = ((const float4*)W)[i];
        __half2 h0 = __floats2half2_rn(w.x, w.y);
        __half2 h1 = __floats2half2_rn(w.z, w.w);
        *(uint2*)(Bs + i * 4) = make_uint2(*(uint32_t*)&h0, *(uint32_t*)&h1);
    }
    cudaGridDependencySynchronize();
    if (F32IN) {
        const float4* in4 = (const float4*)inv;
        #pragma unroll
        for (int k = 0; k < 8; k++) {
            int i = tid + k * 256;
            int row = i >> 4, q = i & 15;
            int gr = rowbase + row;
            float4 v = (gr < NN) ? in4[(size_t)gr * 16 + q] : make_float4(0, 0, 0, 0);
            __half2 h0 = __floats2half2_rn(v.x, v.y);
            __half2 h1 = __floats2half2_rn(v.z, v.w);
            *(uint2*)(As + row * 64 + q * 4) =
                make_uint2(*(uint32_t*)&h0, *(uint32_t*)&h1);
        }
    } else {
        const uint4* in4 = (const uint4*)inv;
        #pragma unroll
        for (int k = 0; k < 4; k++) {
            int i = tid + k * 256;
            int row = i >> 3, q = i & 7;
            int gr = rowbase + row;
            uint4 v = (gr < NN) ? in4[(size_t)gr * 8 + q] : make_uint4(0, 0, 0, 0);
            *(uint4*)(As + row * 64 + q * 8) = v;
        }
    }
    __syncthreads();

    wmma::fragment<wmma::accumulator, 16, 16, 16, float> c[4];
    #pragma unroll
    for (int nt = 0; nt < 4; nt++) wmma::fill_fragment(c[nt], 0.0f);
    const half* arow = As + warp * 16 * 64;
    #pragma unroll
    for (int k0 = 0; k0 < 64; k0 += 16) {
        wmma::fragment<wmma::matrix_a, 16, 16, 16, half, wmma::row_major> a;
        wmma::load_matrix_sync(a, arow + k0, 64);
        #pragma unroll
        for (int nt = 0; nt < 4; nt++) {
            wmma::fragment<wmma::matrix_b, 16, 16, 16, half, wmma::row_major> b;
            wmma::load_matrix_sync(b, Bs + k0 * 64 + nt * 16, 64);
            wmma::mma_sync(c[nt], a, b, c[nt]);
        }
    }
    __syncthreads();

    float* Cst = (float*)sraw + warp * 256;
    int r = lane >> 1;
    int chalf = (lane & 1) * 8;
    int grow = rowbase + warp * 16 + r;
    float di = (grow < NN) ? g_dinv[grow] : 0.f;
    #pragma unroll
    for (int nt = 0; nt < 4; nt++) {
        wmma::store_matrix_sync(Cst, c[nt], 16, wmma::mem_row_major);
        __syncwarp();
        if (grow < NN) {
            float4 v0 = *(const float4*)(Cst + r * 16 + chalf);
            float4 v1 = *(const float4*)(Cst + r * 16 + chalf + 4);
            __half2 h0 = __floats2half2_rn(di * v0.x, di * v0.y);
            __half2 h1 = __floats2half2_rn(di * v0.z, di * v0.w);
            __half2 h2 = __floats2half2_rn(di * v1.x, di * v1.y);
            __half2 h3 = __floats2half2_rn(di * v1.z, di * v1.w);
            *(uint4*)(out + (size_t)grow * 32 + nt * 8 + (lane & 1) * 4) =
                make_uint4(*(uint32_t*)&h0, *(uint32_t*)&h1,
                           *(uint32_t*)&h2, *(uint32_t*)&h3);
        }
        __syncwarp();
    }
}

// ---------------- Aggregation: warp-per-row, half-warp split gathers -------
// Lanes 0-15 cover neighbor row A (uint2 = 4 cols/lane), lanes 16-31 cover
// neighbor row B: ONE LDG.64 fetches TWO neighbor rows. Combine via shfl_xor.
template<bool HALF_OUT>
__global__ void k_agg(const __half2* __restrict__ h, const float* __restrict__ bias,
                      void* __restrict__ outv) {
    int wid  = (blockIdx.x * blockDim.x + threadIdx.x) >> 5;
    int lane = threadIdx.x & 31;
    int hsel = lane >> 4;          // 0: even neighbor, 1: odd neighbor
    int c4   = lane & 15;          // column group: cols 4*c4 .. 4*c4+3
    float4 bb = ((const float4*)bias)[c4];   // input tensor: safe pre-sync
    cudaGridDependencySynchronize();
    if (wid >= NN) return;
    int2 rc   = g_rowcnt[wid];
    int start = rc.x, cnt = rc.y;
    float di  = g_dinv[wid];
    const int* cp = g_col + start;
    const uint2* hq = (const uint2*)h;       // row = 16 uint2
    int cntp = (cnt + 3) & ~3;

    float a0 = 0.f, a1 = 0.f, a2 = 0.f, a3 = 0.f;
    int j = 0;
    for (; j + 16 <= cntp; j += 16) {
        int4 sa = *(const int4*)(cp + j);
        int4 sb = *(const int4*)(cp + j + 4);
        int4 sc = *(const int4*)(cp + j + 8);
        int4 sd = *(const int4*)(cp + j + 12);
        int r0 = hsel ? sa.y : sa.x;
        int r1 = hsel ? sa.w : sa.z;
        int r2 = hsel ? sb.y : sb.x;
        int r3 = hsel ? sb.w : sb.z;
        int r4 = hsel ? sc.y : sc.x;
        int r5 = hsel ? sc.w : sc.z;
        int r6 = hsel ? sd.y : sd.x;
        int r7 = hsel ? sd.w : sd.z;
        uint2 u0 = hq[(size_t)r0 * 16 + c4];
        uint2 u1 = hq[(size_t)r1 * 16 + c4];
        uint2 u2 = hq[(size_t)r2 * 16 + c4];
        uint2 u3 = hq[(size_t)r3 * 16 + c4];
        uint2 u4 = hq[(size_t)r4 * 16 + c4];
        uint2 u5 = hq[(size_t)r5 * 16 + c4];
        uint2 u6 = hq[(size_t)r6 * 16 + c4];
        uint2 u7 = hq[(size_t)r7 * 16 + c4];
        #define ACC(u) { \
            float2 fx = __half22float2(*(__half2*)&(u).x); \
            float2 fy = __half22float2(*(__half2*)&(u).y); \
            a0 += fx.x; a1 += fx.y; a2 += fy.x; a3 += fy.y; }
        ACC(u0) ACC(u1) ACC(u2) ACC(u3) ACC(u4) ACC(u5) ACC(u6) ACC(u7)
    }
    if (j + 8 <= cntp) {
        int4 sa = *(const int4*)(cp + j);
        int4 sb = *(const int4*)(cp + j + 4);
        int r0 = hsel ? sa.y : sa.x;
        int r1 = hsel ? sa.w : sa.z;
        int r2 = hsel ? sb.y : sb.x;
        int r3 = hsel ? sb.w : sb.z;
        uint2 u0 = hq[(size_t)r0 * 16 + c4];
        uint2 u1 = hq[(size_t)r1 * 16 + c4];
        uint2 u2 = hq[(size_t)r2 * 16 + c4];
        uint2 u3 = hq[(size_t)r3 * 16 + c4];
        ACC(u0) ACC(u1) ACC(u2) ACC(u3)
        j += 8;
    }
    if (j < cntp) {
        int4 sa = *(const int4*)(cp + j);
        int r0 = hsel ? sa.y : sa.x;
        int r1 = hsel ? sa.w : sa.z;
        uint2 u0 = hq[(size_t)r0 * 16 + c4];
        uint2 u1 = hq[(size_t)r1 * 16 + c4];
        ACC(u0) ACC(u1)
    }
    #undef ACC

    // combine the two half-warp partials (lane <-> lane^16)
    a0 += __shfl_xor_sync(0xffffffffu, a0, 16);
    a1 += __shfl_xor_sync(0xffffffffu, a1, 16);
    a2 += __shfl_xor_sync(0xffffffffu, a2, 16);
    a3 += __shfl_xor_sync(0xffffffffu, a3, 16);

    // self term + bias + LeakyReLU (identical on both halves)
    uint2 us = hq[(size_t)wid * 16 + c4];
    float2 sx = __half22float2(*(__half2*)&us.x);
    float2 sy = __half22float2(*(__half2*)&us.y);
    float o0 = di * (a0 + sx.x) + bb.x;
    float o1 = di * (a1 + sx.y) + bb.y;
    float o2 = di * (a2 + sy.x) + bb.z;
    float o3 = di * (a3 + sy.y) + bb.w;
    o0 = (o0 >= 0.f) ? o0 : NEG * o0;
    o1 = (o1 >= 0.f) ? o1 : NEG * o1;
    o2 = (o2 >= 0.f) ? o2 : NEG * o2;
    o3 = (o3 >= 0.f) ? o3 : NEG * o3;

    if (hsel == 0) {                       // lanes 0-15 write the row
        if (HALF_OUT) {
            __half2 q0 = __floats2half2_rn(o0, o1);
            __half2 q1 = __floats2half2_rn(o2, o3);
            ((uint2*)outv)[(size_t)wid * 16 + c4] =
                make_uint2(*(uint32_t*)&q0, *(uint32_t*)&q1);
        } else {
            ((float4*)outv)[(size_t)wid * 16 + c4] = make_float4(o0, o1, o2, o3);
        }
    }
}

// ---------------- launch (PDL-chained) --------------------------------------
template<typename K, typename... Args>
static inline void pdl_launch(K kern, int grid, int block, Args... args) {
    cudaLaunchConfig_t cfg = {};
    cfg.gridDim = dim3(grid);
    cfg.blockDim = dim3(block);
    cudaLaunchAttribute attr[1];
    attr[0].id = cudaLaunchAttributeProgrammaticStreamSerialization;
    attr[0].val.programmaticStreamSerializationAllowed = 1;
    cfg.attrs = attr;
    cfg.numAttrs = 1;
    cudaLaunchKernelEx(&cfg, kern, args...);
}

extern "C" void kernel_launch(void* const* d_in, const int* in_sizes, int n_in,
                              void* d_out, int out_size) {
    (void)in_sizes; (void)n_in; (void)out_size;
    const float* x  = (const float*)d_in[0];
    const int*   ei = (const int*)d_in[1];
    const int* src = ei;
    const int* dst = ei + EE;
    const float* Wt[4] = { (const float*)d_in[2], (const float*)d_in[4],
                           (const float*)d_in[6], (const float*)d_in[8] };
    const float* bt[4] = { (const float*)d_in[3], (const float*)d_in[5],
                           (const float*)d_in[7], (const float*)d_in[9] };

    __half2 *p_h, *p_a, *p_b;
    cudaGetSymbolAddress((void**)&p_h, g_h);
    cudaGetSymbolAddress((void**)&p_a, g_bufA);
    cudaGetSymbolAddress((void**)&p_b, g_bufB);

    const int NB_SCAN = (NN + 1023) / 1024;    // 98
    const int NB_N256 = (NN + 255) / 256;      // 391
    const int NB_E8   = (EE / 8 + 255) / 256;  // 782

    // CSR build
    k_zero_cnt<<<NB_N256, 256>>>();
    pdl_launch(k_hist, NB_E8, 256, dst);
    pdl_launch(k_scanA, NB_SCAN, 1024);
    pdl_launch(k_scanB, 1, 32, NB_SCAN);
    pdl_launch(k_scanC, NB_N256, 256);
    pdl_launch(k_scatter, NB_E8, 256, src, dst);

    const int GEMM_BLOCKS = (NN + 127) / 128;  // 782
    const int AGG_BLOCKS  = NN / 8;            // 12500

    // layer 1
    pdl_launch(k_gemm_wmma<true >, GEMM_BLOCKS, 256, (const void*)x, Wt[0], p_h);
    pdl_launch(k_agg<true >, AGG_BLOCKS, 256, (const __half2*)p_h, bt[0], (void*)p_a);
    // layer 2
    pdl_launch(k_gemm_wmma<false>, GEMM_BLOCKS, 256, (const void*)p_a, Wt[1], p_h);
    pdl_launch(k_agg<true >, AGG_BLOCKS, 256, (const __half2*)p_h, bt[1], (void*)p_b);
    // layer 3
    pdl_launch(k_gemm_wmma<false>, GEMM_BLOCKS, 256, (const void*)p_b, Wt[2], p_h);
    pdl_launch(k_agg<true >, AGG_BLOCKS, 256, (const __half2*)p_h, bt[2], (void*)p_a);
    // layer 4
    pdl_launch(k_gemm_wmma<false>, GEMM_BLOCKS, 256, (const void*)p_a, Wt[3], p_h);
    pdl_launch(k_agg<false>, AGG_BLOCKS, 256, (const __half2*)p_h, bt[3], d_out);
}

// round 15
// speedup vs baseline: 1.0321x; 1.0321x over previous
#include <cuda_runtime.h>
#include <cuda_fp16.h>
#include <mma.h>
#include <math.h>
#include <stdint.h>

using namespace nvcuda;

#define NN 100000
#define EE 1600000
#define NEG 0.01f
#define COLCAP 2000000   // EE + 3*NN padding worst case, rounded up

// ---------------- scratch (device globals) ---------------------------------
__device__ __half2 g_h[(NN + 1) * 32];   // row NN stays zero forever (pad target)
__device__ __half2 g_bufA[NN * 32];
__device__ __half2 g_bufB[NN * 32];
__device__ int   g_cnt[NN];              // ==0 at entry (module init / k_scan restores)
__device__ int2  g_rowcnt[NN];           // {rowptr, cnt} packed, one LDG.64
__device__ int   g_pos[NN];
__device__ int   g_col[COLCAP];
__device__ float g_dinv[NN];
__device__ int   g_total;                // ==0 at entry (module init / k_scatter restores)

// ---------------- CSR build ------------------------------------------------
__global__ void k_hist(const int* __restrict__ dst) {
    cudaGridDependencySynchronize();
    int t = blockIdx.x * blockDim.x + threadIdx.x;
    if (t * 8 < EE) {
        int4 d0 = ((const int4*)dst)[t * 2];
        int4 d1 = ((const int4*)dst)[t * 2 + 1];
        atomicAdd(&g_cnt[d0.x], 1);
        atomicAdd(&g_cnt[d0.y], 1);
        atomicAdd(&g_cnt[d0.z], 1);
        atomicAdd(&g_cnt[d0.w], 1);
        atomicAdd(&g_cnt[d1.x], 1);
        atomicAdd(&g_cnt[d1.y], 1);
        atomicAdd(&g_cnt[d1.z], 1);
        atomicAdd(&g_cnt[d1.w], 1);
    }
}

// Fused scan: per-block padded prefix + atomic block-offset grab + rowcnt/pos
// finalize + pad fill + dinv + g_cnt re-zero. Block offsets are assigned in
// whatever order blocks run — CSR layout is valid either way (slot order within
// a row is already nondeterministic via the scatter atomics).
__global__ void k_scan() {
    __shared__ int s[1024];
    __shared__ int sbase;
    cudaGridDependencySynchronize();
    int tid = threadIdx.x;
    int i = blockIdx.x * 1024 + tid;
    int v = (i < NN) ? g_cnt[i] : 0;
    if (i < NN) {
        g_dinv[i] = rsqrtf((float)(v + 1));
        g_cnt[i] = 0;                      // restore invariant for next replay
    }
    int vp = (v + 3) & ~3;                 // padded count
    s[tid] = vp;
    __syncthreads();
    #pragma unroll
    for (int off = 1; off < 1024; off <<= 1) {
        int t = (tid >= off) ? s[tid - off] : 0;
        __syncthreads();
        s[tid] += t;
        __syncthreads();
    }
    if (tid == 1023) sbase = atomicAdd(&g_total, s[1023]);
    __syncthreads();
    if (i < NN) {
        int rp = sbase + s[tid] - vp;      // exclusive padded prefix
        g_rowcnt[i] = make_int2(rp, v);
        g_pos[i] = rp;
        for (int k = v; k < vp; k++) g_col[rp + k] = NN;  // dummy -> zero row
    }
}

__global__ void k_scatter(const int* __restrict__ src, const int* __restrict__ dst) {
    cudaGridDependencySynchronize();
    int t = blockIdx.x * blockDim.x + threadIdx.x;
    if (t == 0) g_total = 0;               // reset cursor for next replay
    if (t * 8 < EE) {
        int4 d0 = ((const int4*)dst)[t * 2];
        int4 d1 = ((const int4*)dst)[t * 2 + 1];
        int4 s0 = ((const int4*)src)[t * 2];
        int4 s1 = ((const int4*)src)[t * 2 + 1];
        int p0 = atomicAdd(&g_pos[d0.x], 1);
        int p1 = atomicAdd(&g_pos[d0.y], 1);
        int p2 = atomicAdd(&g_pos[d0.z], 1);
        int p3 = atomicAdd(&g_pos[d0.w], 1);
        int p4 = atomicAdd(&g_pos[d1.x], 1);
        int p5 = atomicAdd(&g_pos[d1.y], 1);
        int p6 = atomicAdd(&g_pos[d1.z], 1);
        int p7 = atomicAdd(&g_pos[d1.w], 1);
        g_col[p0] = s0.x;
        g_col[p1] = s0.y;
        g_col[p2] = s0.z;
        g_col[p3] = s0.w;
        g_col[p4] = s1.x;
        g_col[p5] = s1.y;
        g_col[p6] = s1.z;
        g_col[p7] = s1.w;
    }
}

// ---------------- WMMA GEMM: h'[N,64](fp16) = dinv[row]*(in @ W) -----------
template<bool F32IN>
__global__ void __launch_bounds__(256) k_gemm_wmma(
    const void* __restrict__ inv, const float* __restrict__ W,
    __half2* __restrict__ out) {
    __shared__ __align__(16) char sraw[24576];
    half* As = (half*)sraw;             // 128 x 64 (ldm 64)
    half* Bs = (half*)(sraw + 16384);   // 64 x 64  (ldm 64)
    int tid  = threadIdx.x;
    int warp = tid >> 5, lane = tid & 31;
    int rowbase = blockIdx.x * 128;

    #pragma unroll
    for (int k = 0; k < 4; k++) {
        int i = tid + k * 256;
        float4 w = ((const float4*)W)[i];
        __half2 h0 = __floats2half2_rn(w.x, w.y);
        __half2 h1 = __floats2half2_rn(w.z, w.w);
        *(uint2*)(Bs + i * 4) = make_uint2(*(uint32_t*)&h0, *(uint32_t*)&h1);
    }
    cudaGridDependencySynchronize();
    if (F32IN) {
        const float4* in4 = (const float4*)inv;
        #pragma unroll
        for (int k = 0; k < 8; k++) {
            int i = tid + k * 256;
            int row = i >> 4, q = i & 15;
            int gr = rowbase + row;
            float4 v = (gr < NN) ? in4[(size_t)gr * 16 + q] : make_float4(0, 0, 0, 0);
            __half2 h0 = __floats2half2_rn(v.x, v.y);
            __half2 h1 = __floats2half2_rn(v.z, v.w);
            *(uint2*)(As + row * 64 + q * 4) =
                make_uint2(*(uint32_t*)&h0, *(uint32_t*)&h1);
        }
    } else {
        const uint4* in4 = (const uint4*)inv;
        #pragma unroll
        for (int k = 0; k < 4; k++) {
            int i = tid + k * 256;
            int row = i >> 3, q = i & 7;
            int gr = rowbase + row;
            uint4 v = (gr < NN) ? in4[(size_t)gr * 8 + q] : make_uint4(0, 0, 0, 0);
            *(uint4*)(As + row * 64 + q * 8) = v;
        }
    }
    __syncthreads();

    wmma::fragment<wmma::accumulator, 16, 16, 16, float> c[4];
    #pragma unroll
    for (int nt = 0; nt < 4; nt++) wmma::fill_fragment(c[nt], 0.0f);
    const half* arow = As + warp * 16 * 64;
    #pragma unroll
    for (int k0 = 0; k0 < 64; k0 += 16) {
        wmma::fragment<wmma::matrix_a, 16, 16, 16, half, wmma::row_major> a;
        wmma::load_matrix_sync(a, arow + k0, 64);
        #pragma unroll
        for (int nt = 0; nt < 4; nt++) {
            wmma::fragment<wmma::matrix_b, 16, 16, 16, half, wmma::row_major> b;
            wmma::load_matrix_sync(b, Bs + k0 * 64 + nt * 16, 64);
            wmma::mma_sync(c[nt], a, b, c[nt]);
        }
    }
    __syncthreads();

    float* Cst = (float*)sraw + warp * 256;
    int r = lane >> 1;
    int chalf = (lane & 1) * 8;
    int grow = rowbase + warp * 16 + r;
    float di = (grow < NN) ? g_dinv[grow] : 0.f;
    #pragma unroll
    for (int nt = 0; nt < 4; nt++) {
        wmma::store_matrix_sync(Cst, c[nt], 16, wmma::mem_row_major);
        __syncwarp();
        if (grow < NN) {
            float4 v0 = *(const float4*)(Cst + r * 16 + chalf);
            float4 v1 = *(const float4*)(Cst + r * 16 + chalf + 4);
            __half2 h0 = __floats2half2_rn(di * v0.x, di * v0.y);
            __half2 h1 = __floats2half2_rn(di * v0.z, di * v0.w);
            __half2 h2 = __floats2half2_rn(di * v1.x, di * v1.y);
            __half2 h3 = __floats2half2_rn(di * v1.z, di * v1.w);
            *(uint4*)(out + (size_t)grow * 32 + nt * 8 + (lane & 1) * 4) =
                make_uint4(*(uint32_t*)&h0, *(uint32_t*)&h1,
                           *(uint32_t*)&h2, *(uint32_t*)&h3);
        }
        __syncwarp();
    }
}

// ---------------- Aggregation: warp-per-row, 16-wide gather batches --------
template<bool HALF_OUT>
__global__ void k_agg(const __half2* __restrict__ h, const float* __restrict__ bias,
                      void* __restrict__ outv) {
    int wid  = (blockIdx.x * blockDim.x + threadIdx.x) >> 5;
    int lane = threadIdx.x & 31;
    float2 bb = ((const float2*)bias)[lane];   // input tensor: safe pre-sync
    cudaGridDependencySynchronize();
    if (wid >= NN) return;
    int2 rc   = g_rowcnt[wid];
    int start = rc.x, cnt = rc.y;
    float di  = g_dinv[wid];
    const int* cp = g_col + start;
    int cntp = (cnt + 3) & ~3;

    float a0 = 0.f, a1 = 0.f;
    int j = 0;
    for (; j + 16 <= cntp; j += 16) {
        int4 sa = *(const int4*)(cp + j);
        int4 sb = *(const int4*)(cp + j + 4);
        int4 sc = *(const int4*)(cp + j + 8);
        int4 sd = *(const int4*)(cp + j + 12);
        __half2 v0 = h[sa.x * 32 + lane];
        __half2 v1 = h[sa.y * 32 + lane];
        __half2 v2 = h[sa.z * 32 + lane];
        __half2 v3 = h[sa.w * 32 + lane];
        __half2 v4 = h[sb.x * 32 + lane];
        __half2 v5 = h[sb.y * 32 + lane];
        __half2 v6 = h[sb.z * 32 + lane];
        __half2 v7 = h[sb.w * 32 + lane];
        __half2 v8 = h[sc.x * 32 + lane];
        __half2 v9 = h[sc.y * 32 + lane];
        __half2 va = h[sc.z * 32 + lane];
        __half2 vb = h[sc.w * 32 + lane];
        __half2 vc = h[sd.x * 32 + lane];
        __half2 vd = h[sd.y * 32 + lane];
        __half2 ve = h[sd.z * 32 + lane];
        __half2 vf = h[sd.w * 32 + lane];
        float2 f0 = __half22float2(v0), f1 = __half22float2(v1);
        float2 f2 = __half22float2(v2), f3 = __half22float2(v3);
        float2 f4 = __half22float2(v4), f5 = __half22float2(v5);
        float2 f6 = __half22float2(v6), f7 = __half22float2(v7);
        float2 f8 = __half22float2(v8), f9 = __half22float2(v9);
        float2 fa = __half22float2(va), fb = __half22float2(vb);
        float2 fc = __half22float2(vc), fd = __half22float2(vd);
        float2 fe = __half22float2(ve), ff = __half22float2(vf);
        a0 += f0.x + f1.x + f2.x + f3.x + f4.x + f5.x + f6.x + f7.x
            + f8.x + f9.x + fa.x + fb.x + fc.x + fd.x + fe.x + ff.x;
        a1 += f0.y + f1.y + f2.y + f3.y + f4.y + f5.y + f6.y + f7.y
            + f8.y + f9.y + fa.y + fb.y + fc.y + fd.y + fe.y + ff.y;
    }
    if (j + 8 <= cntp) {
        int4 sa = *(const int4*)(cp + j);
        int4 sb = *(const int4*)(cp + j + 4);
        __half2 v0 = h[sa.x * 32 + lane];
        __half2 v1 = h[sa.y * 32 + lane];
        __half2 v2 = h[sa.z * 32 + lane];
        __half2 v3 = h[sa.w * 32 + lane];
        __half2 v4 = h[sb.x * 32 + lane];
        __half2 v5 = h[sb.y * 32 + lane];
        __half2 v6 = h[sb.z * 32 + lane];
        __half2 v7 = h[sb.w * 32 + lane];
        float2 f0 = __half22float2(v0), f1 = __half22float2(v1);
        float2 f2 = __half22float2(v2), f3 = __half22float2(v3);
        float2 f4 = __half22float2(v4), f5 = __half22float2(v5);
        float2 f6 = __half22float2(v6), f7 = __half22float2(v7);
        a0 += f0.x + f1.x + f2.x + f3.x + f4.x + f5.x + f6.x + f7.x;
        a1 += f0.y + f1.y + f2.y + f3.y + f4.y + f5.y + f6.y + f7.y;
        j += 8;
    }
    if (j < cntp) {
        int4 sa = *(const int4*)(cp + j);
        __half2 v0 = h[sa.x * 32 + lane];
        __half2 v1 = h[sa.y * 32 + lane];
        __half2 v2 = h[sa.z * 32 + lane];
        __half2 v3 = h[sa.w * 32 + lane];
        float2 f0 = __half22float2(v0), f1 = __half22float2(v1);
        float2 f2 = __half22float2(v2), f3 = __half22float2(v3);
        a0 += f0.x + f1.x + f2.x + f3.x;
        a1 += f0.y + f1.y + f2.y + f3.y;
    }

    float2 hs = __half22float2(h[wid * 32 + lane]);
    float o0 = di * (a0 + hs.x) + bb.x;
    float o1 = di * (a1 + hs.y) + bb.y;
    o0 = (o0 >= 0.f) ? o0 : NEG * o0;
    o1 = (o1 >= 0.f) ? o1 : NEG * o1;
    if (HALF_OUT) {
        ((__half2*)outv)[(size_t)wid * 32 + lane] = __floats2half2_rn(o0, o1);
    } else {
        float2 oo; oo.x = o0; oo.y = o1;
        ((float2*)outv)[(size_t)wid * 32 + lane] = oo;
    }
}

// ---------------- launch (PDL-chained) --------------------------------------
template<typename K, typename... Args>
static inline void pdl_launch(K kern, int grid, int block, Args... args) {
    cudaLaunchConfig_t cfg = {};
    cfg.gridDim = dim3(grid);
    cfg.blockDim = dim3(block);
    cudaLaunchAttribute attr[1];
    attr[0].id = cudaLaunchAttributeProgrammaticStreamSerialization;
    attr[0].val.programmaticStreamSerializationAllowed = 1;
    cfg.attrs = attr;
    cfg.numAttrs = 1;
    cudaLaunchKernelEx(&cfg, kern, args...);
}

extern "C" void kernel_launch(void* const* d_in, const int* in_sizes, int n_in,
                              void* d_out, int out_size) {
    (void)in_sizes; (void)n_in; (void)out_size;
    const float* x  = (const float*)d_in[0];
    const int*   ei = (const int*)d_in[1];
    const int* src = ei;
    const int* dst = ei + EE;
    const float* Wt[4] = { (const float*)d_in[2], (const float*)d_in[4],
                           (const float*)d_in[6], (const float*)d_in[8] };
    const float* bt[4] = { (const float*)d_in[3], (const float*)d_in[5],
                           (const float*)d_in[7], (const float*)d_in[9] };

    __half2 *p_h, *p_a, *p_b;
    cudaGetSymbolAddress((void**)&p_h, g_h);
    cudaGetSymbolAddress((void**)&p_a, g_bufA);
    cudaGetSymbolAddress((void**)&p_b, g_bufB);

    const int NB_SCAN = (NN + 1023) / 1024;    // 98
    const int NB_E8   = (EE / 8 + 255) / 256;  // 782

    // CSR build — g_cnt==0 and g_total==0 at entry (module init / restored)
    k_hist<<<NB_E8, 256>>>(dst);               // head of chain: plain launch
    pdl_launch(k_scan, NB_SCAN, 1024);
    pdl_launch(k_scatter, NB_E8, 256, src, dst);

    const int GEMM_BLOCKS = (NN + 127) / 128;  // 782
    const int AGG_BLOCKS  = NN / 8;            // 12500

    // layer 1
    pdl_launch(k_gemm_wmma<true >, GEMM_BLOCKS, 256, (const void*)x, Wt[0], p_h);
    pdl_launch(k_agg<true >, AGG_BLOCKS, 256, (const __half2*)p_h, bt[0], (void*)p_a);
    // layer 2
    pdl_launch(k_gemm_wmma<false>, GEMM_BLOCKS, 256, (const void*)p_a, Wt[1], p_h);
    pdl_launch(k_agg<true >, AGG_BLOCKS, 256, (const __half2*)p_h, bt[1], (void*)p_b);
    // layer 3
    pdl_launch(k_gemm_wmma<false>, GEMM_BLOCKS, 256, (const void*)p_b, Wt[2], p_h);
    pdl_launch(k_agg<true >, AGG_BLOCKS, 256, (const __half2*)p_h, bt[2], (void*)p_a);
    // layer 4
    pdl_launch(k_gemm_wmma<false>, GEMM_BLOCKS, 256, (const void*)p_a, Wt[3], p_h);
    pdl_launch(k_agg<false>, AGG_BLOCKS, 256, (const __half2*)p_h, bt[3], d_out);
}

// round 16
// speedup vs baseline: 1.3323x; 1.2909x over previous
#include <cuda_runtime.h>
#include <cuda_fp16.h>
#include <mma.h>
#include <math.h>
#include <stdint.h>

using namespace nvcuda;

#define NN 100000
#define EE 1600000
#define NEG 0.01f
#define COLCAP 2000000   // EE + 3*NN padding worst case, rounded up
#define ASTRIDE 72       // padded smem row stride in halves (144 B = 36 banks)

// ---------------- scratch (device globals) ---------------------------------
__device__ __half2 g_h[(NN + 1) * 32];   // row NN stays zero forever (pad target)
__device__ __half2 g_bufA[NN * 32];
__device__ __half2 g_bufB[NN * 32];
__device__ int   g_cnt[NN];              // ==0 at entry (module init / k_scan restores)
__device__ int2  g_rowcnt[NN];           // {rowptr, cnt} packed, one LDG.64
__device__ int   g_pos[NN];
__device__ int   g_col[COLCAP];
__device__ float g_dinv[NN];
__device__ int   g_total;                // ==0 at entry (module init / k_scatter restores)

// ---------------- CSR build ------------------------------------------------
__global__ void k_hist(const int* __restrict__ dst) {
    cudaGridDependencySynchronize();
    int t = blockIdx.x * blockDim.x + threadIdx.x;
    if (t * 8 < EE) {
        int4 d0 = ((const int4*)dst)[t * 2];
        int4 d1 = ((const int4*)dst)[t * 2 + 1];
        atomicAdd(&g_cnt[d0.x], 1);
        atomicAdd(&g_cnt[d0.y], 1);
        atomicAdd(&g_cnt[d0.z], 1);
        atomicAdd(&g_cnt[d0.w], 1);
        atomicAdd(&g_cnt[d1.x], 1);
        atomicAdd(&g_cnt[d1.y], 1);
        atomicAdd(&g_cnt[d1.z], 1);
        atomicAdd(&g_cnt[d1.w], 1);
    }
}

// Fused scan: per-block padded prefix + atomic block-offset grab + rowcnt/pos
// finalize + pad fill + dinv + g_cnt re-zero.
__global__ void k_scan() {
    __shared__ int s[1024];
    __shared__ int sbase;
    cudaGridDependencySynchronize();
    int tid = threadIdx.x;
    int i = blockIdx.x * 1024 + tid;
    int v = (i < NN) ? g_cnt[i] : 0;
    if (i < NN) {
        g_dinv[i] = rsqrtf((float)(v + 1));
        g_cnt[i] = 0;                      // restore invariant for next replay
    }
    int vp = (v + 3) & ~3;                 // padded count
    s[tid] = vp;
    __syncthreads();
    #pragma unroll
    for (int off = 1; off < 1024; off <<= 1) {
        int t = (tid >= off) ? s[tid - off] : 0;
        __syncthreads();
        s[tid] += t;
        __syncthreads();
    }
    if (tid == 1023) sbase = atomicAdd(&g_total, s[1023]);
    __syncthreads();
    if (i < NN) {
        int rp = sbase + s[tid] - vp;      // exclusive padded prefix
        g_rowcnt[i] = make_int2(rp, v);
        g_pos[i] = rp;
        for (int k = v; k < vp; k++) g_col[rp + k] = NN;  // dummy -> zero row
    }
}

__global__ void k_scatter(const int* __restrict__ src, const int* __restrict__ dst) {
    cudaGridDependencySynchronize();
    int t = blockIdx.x * blockDim.x + threadIdx.x;
    if (t == 0) g_total = 0;               // reset cursor for next replay
    if (t * 8 < EE) {
        int4 d0 = ((const int4*)dst)[t * 2];
        int4 d1 = ((const int4*)dst)[t * 2 + 1];
        int4 s0 = ((const int4*)src)[t * 2];
        int4 s1 = ((const int4*)src)[t * 2 + 1];
        int p0 = atomicAdd(&g_pos[d0.x], 1);
        int p1 = atomicAdd(&g_pos[d0.y], 1);
        int p2 = atomicAdd(&g_pos[d0.z], 1);
        int p3 = atomicAdd(&g_pos[d0.w], 1);
        int p4 = atomicAdd(&g_pos[d1.x], 1);
        int p5 = atomicAdd(&g_pos[d1.y], 1);
        int p6 = atomicAdd(&g_pos[d1.z], 1);
        int p7 = atomicAdd(&g_pos[d1.w], 1);
        g_col[p0] = s0.x;
        g_col[p1] = s0.y;
        g_col[p2] = s0.z;
        g_col[p3] = s0.w;
        g_col[p4] = s1.x;
        g_col[p5] = s1.y;
        g_col[p6] = s1.z;
        g_col[p7] = s1.w;
    }
}

// ---------------- WMMA GEMM: h'[N,64](fp16) = dinv[row]*(in @ W) -----------
// Padded smem stride (72 halves = 144 B) kills the 8-way LDSM bank conflicts
// the profiler showed (L1 66%, tensor 4.6% with the 128 B stride).
template<bool F32IN>
__global__ void __launch_bounds__(256) k_gemm_wmma(
    const void* __restrict__ inv, const float* __restrict__ W,
    __half2* __restrict__ out) {
    __shared__ __align__(16) char sraw[(128 + 64) * ASTRIDE * 2 + 256];
    half* As = (half*)sraw;                              // 128 x 72 halves
    half* Bs = (half*)sraw + 128 * ASTRIDE;              // 64 x 72 halves
    int tid  = threadIdx.x;
    int warp = tid >> 5, lane = tid & 31;
    int rowbase = blockIdx.x * 128;

    #pragma unroll
    for (int k = 0; k < 4; k++) {
        int i = tid + k * 256;               // 1024 float4 = W
        int r = i >> 4, c = i & 15;          // row r, cols 4c..4c+3
        float4 w = ((const float4*)W)[i];
        __half2 h0 = __floats2half2_rn(w.x, w.y);
        __half2 h1 = __floats2half2_rn(w.z, w.w);
        *(uint2*)(Bs + r * ASTRIDE + c * 4) =
            make_uint2(*(uint32_t*)&h0, *(uint32_t*)&h1);
    }
    cudaGridDependencySynchronize();
    if (F32IN) {
        const float4* in4 = (const float4*)inv;
        #pragma unroll
        for (int k = 0; k < 8; k++) {
            int i = tid + k * 256;
            int row = i >> 4, q = i & 15;
            int gr = rowbase + row;
            float4 v = (gr < NN) ? in4[(size_t)gr * 16 + q] : make_float4(0, 0, 0, 0);
            __half2 h0 = __floats2half2_rn(v.x, v.y);
            __half2 h1 = __floats2half2_rn(v.z, v.w);
            *(uint2*)(As + row * ASTRIDE + q * 4) =
                make_uint2(*(uint32_t*)&h0, *(uint32_t*)&h1);
        }
    } else {
        const uint4* in4 = (const uint4*)inv;
        #pragma unroll
        for (int k = 0; k < 4; k++) {
            int i = tid + k * 256;
            int row = i >> 3, q = i & 7;
            int gr = rowbase + row;
            uint4 v = (gr < NN) ? in4[(size_t)gr * 8 + q] : make_uint4(0, 0, 0, 0);
            *(uint4*)(As + row * ASTRIDE + q * 8) = v;   // 144B row: 16B aligned
        }
    }
    __syncthreads();

    wmma::fragment<wmma::accumulator, 16, 16, 16, float> c[4];
    #pragma unroll
    for (int nt = 0; nt < 4; nt++) wmma::fill_fragment(c[nt], 0.0f);
    const half* arow = As + warp * 16 * ASTRIDE;
    #pragma unroll
    for (int k0 = 0; k0 < 64; k0 += 16) {
        wmma::fragment<wmma::matrix_a, 16, 16, 16, half, wmma::row_major> a;
        wmma::load_matrix_sync(a, arow + k0, ASTRIDE);
        #pragma unroll
        for (int nt = 0; nt < 4; nt++) {
            wmma::fragment<wmma::matrix_b, 16, 16, 16, half, wmma::row_major> b;
            wmma::load_matrix_sync(b, Bs + k0 * ASTRIDE + nt * 16, ASTRIDE);
            wmma::mma_sync(c[nt], a, b, c[nt]);
        }
    }
    __syncthreads();

    float* Cst = (float*)sraw + warp * 256;
    int r = lane >> 1;
    int chalf = (lane & 1) * 8;
    int grow = rowbase + warp * 16 + r;
    float di = (grow < NN) ? g_dinv[grow] : 0.f;
    #pragma unroll
    for (int nt = 0; nt < 4; nt++) {
        wmma::store_matrix_sync(Cst, c[nt], 16, wmma::mem_row_major);
        __syncwarp();
        if (grow < NN) {
            float4 v0 = *(const float4*)(Cst + r * 16 + chalf);
            float4 v1 = *(const float4*)(Cst + r * 16 + chalf + 4);
            __half2 h0 = __floats2half2_rn(di * v0.x, di * v0.y);
            __half2 h1 = __floats2half2_rn(di * v0.z, di * v0.w);
            __half2 h2 = __floats2half2_rn(di * v1.x, di * v1.y);
            __half2 h3 = __floats2half2_rn(di * v1.z, di * v1.w);
            *(uint4*)(out + (size_t)grow * 32 + nt * 8 + (lane & 1) * 4) =
                make_uint4(*(uint32_t*)&h0, *(uint32_t*)&h1,
                           *(uint32_t*)&h2, *(uint32_t*)&h3);
        }
        __syncwarp();
    }
}

// ---------------- Aggregation: warp-per-row, 16-wide gather batches --------
template<bool HALF_OUT>
__global__ void k_agg(const __half2* __restrict__ h, const float* __restrict__ bias,
                      void* __restrict__ outv) {
    int wid  = (blockIdx.x * blockDim.x + threadIdx.x) >> 5;
    int lane = threadIdx.x & 31;
    float2 bb = ((const float2*)bias)[lane];   // input tensor: safe pre-sync
    cudaGridDependencySynchronize();
    if (wid >= NN) return;
    int2 rc   = g_rowcnt[wid];
    int start = rc.x, cnt = rc.y;
    float di  = g_dinv[wid];
    const int* cp = g_col + start;
    int cntp = (cnt + 3) & ~3;

    float a0 = 0.f, a1 = 0.f;
    int j = 0;
    for (; j + 16 <= cntp; j += 16) {
        int4 sa = *(const int4*)(cp + j);
        int4 sb = *(const int4*)(cp + j + 4);
        int4 sc = *(const int4*)(cp + j + 8);
        int4 sd = *(const int4*)(cp + j + 12);
        __half2 v0 = h[sa.x * 32 + lane];
        __half2 v1 = h[sa.y * 32 + lane];
        __half2 v2 = h[sa.z * 32 + lane];
        __half2 v3 = h[sa.w * 32 + lane];
        __half2 v4 = h[sb.x * 32 + lane];
        __half2 v5 = h[sb.y * 32 + lane];
        __half2 v6 = h[sb.z * 32 + lane];
        __half2 v7 = h[sb.w * 32 + lane];
        __half2 v8 = h[sc.x * 32 + lane];
        __half2 v9 = h[sc.y * 32 + lane];
        __half2 va = h[sc.z * 32 + lane];
        __half2 vb = h[sc.w * 32 + lane];
        __half2 vc = h[sd.x * 32 + lane];
        __half2 vd = h[sd.y * 32 + lane];
        __half2 ve = h[sd.z * 32 + lane];
        __half2 vf = h[sd.w * 32 + lane];
        float2 f0 = __half22float2(v0), f1 = __half22float2(v1);
        float2 f2 = __half22float2(v2), f3 = __half22float2(v3);
        float2 f4 = __half22float2(v4), f5 = __half22float2(v5);
        float2 f6 = __half22float2(v6), f7 = __half22float2(v7);
        float2 f8 = __half22float2(v8), f9 = __half22float2(v9);
        float2 fa = __half22float2(va), fb = __half22float2(vb);
        float2 fc = __half22float2(vc), fd = __half22float2(vd);
        float2 fe = __half22float2(ve), ff = __half22float2(vf);
        a0 += f0.x + f1.x + f2.x + f3.x + f4.x + f5.x + f6.x + f7.x
            + f8.x + f9.x + fa.x + fb.x + fc.x + fd.x + fe.x + ff.x;
        a1 += f0.y + f1.y + f2.y + f3.y + f4.y + f5.y + f6.y + f7.y
            + f8.y + f9.y + fa.y + fb.y + fc.y + fd.y + fe.y + ff.y;
    }
    if (j + 8 <= cntp) {
        int4 sa = *(const int4*)(cp + j);
        int4 sb = *(const int4*)(cp + j + 4);
        __half2 v0 = h[sa.x * 32 + lane];
        __half2 v1 = h[sa.y * 32 + lane];
        __half2 v2 = h[sa.z * 32 + lane];
        __half2 v3 = h[sa.w * 32 + lane];
        __half2 v4 = h[sb.x * 32 + lane];
        __half2 v5 = h[sb.y * 32 + lane];
        __half2 v6 = h[sb.z * 32 + lane];
        __half2 v7 = h[sb.w * 32 + lane];
        float2 f0 = __half22float2(v0), f1 = __half22float2(v1);
        float2 f2 = __half22float2(v2), f3 = __half22float2(v3);
        float2 f4 = __half22float2(v4), f5 = __half22float2(v5);
        float2 f6 = __half22float2(v6), f7 = __half22float2(v7);
        a0 += f0.x + f1.x + f2.x + f3.x + f4.x + f5.x + f6.x + f7.x;
        a1 += f0.y + f1.y + f2.y + f3.y + f4.y + f5.y + f6.y + f7.y;
        j += 8;
    }
    if (j < cntp) {
        int4 sa = *(const int4*)(cp + j);
        __half2 v0 = h[sa.x * 32 + lane];
        __half2 v1 = h[sa.y * 32 + lane];
        __half2 v2 = h[sa.z * 32 + lane];
        __half2 v3 = h[sa.w * 32 + lane];
        float2 f0 = __half22float2(v0), f1 = __half22float2(v1);
        float2 f2 = __half22float2(v2), f3 = __half22float2(v3);
        a0 += f0.x + f1.x + f2.x + f3.x;
        a1 += f0.y + f1.y + f2.y + f3.y;
    }

    float2 hs = __half22float2(h[wid * 32 + lane]);
    float o0 = di * (a0 + hs.x) + bb.x;
    float o1 = di * (a1 + hs.y) + bb.y;
    o0 = (o0 >= 0.f) ? o0 : NEG * o0;
    o1 = (o1 >= 0.f) ? o1 : NEG * o1;
    if (HALF_OUT) {
        ((__half2*)outv)[(size_t)wid * 32 + lane] = __floats2half2_rn(o0, o1);
    } else {
        float2 oo; oo.x = o0; oo.y = o1;
        ((float2*)outv)[(size_t)wid * 32 + lane] = oo;
    }
}

// ---------------- launch (PDL-chained) --------------------------------------
template<typename K, typename... Args>
static inline void pdl_launch(K kern, int grid, int block, Args... args) {
    cudaLaunchConfig_t cfg = {};
    cfg.gridDim = dim3(grid);
    cfg.blockDim = dim3(block);
    cudaLaunchAttribute attr[1];
    attr[0].id = cudaLaunchAttributeProgrammaticStreamSerialization;
    attr[0].val.programmaticStreamSerializationAllowed = 1;
    cfg.attrs = attr;
    cfg.numAttrs = 1;
    cudaLaunchKernelEx(&cfg, kern, args...);
}

extern "C" void kernel_launch(void* const* d_in, const int* in_sizes, int n_in,
                              void* d_out, int out_size) {
    (void)in_sizes; (void)n_in; (void)out_size;
    const float* x  = (const float*)d_in[0];
    const int*   ei = (const int*)d_in[1];
    const int* src = ei;
    const int* dst = ei + EE;
    const float* Wt[4] = { (const float*)d_in[2], (const float*)d_in[4],
                           (const float*)d_in[6], (const float*)d_in[8] };
    const float* bt[4] = { (const float*)d_in[3], (const float*)d_in[5],
                           (const float*)d_in[7], (const float*)d_in[9] };

    __half2 *p_h, *p_a, *p_b;
    cudaGetSymbolAddress((void**)&p_h, g_h);
    cudaGetSymbolAddress((void**)&p_a, g_bufA);
    cudaGetSymbolAddress((void**)&p_b, g_bufB);

    const int NB_SCAN = (NN + 1023) / 1024;    // 98
    const int NB_E8   = (EE / 8 + 255) / 256;  // 782

    // CSR build — g_cnt==0 and g_total==0 at entry (module init / restored)
    k_hist<<<NB_E8, 256>>>(dst);               // head of chain: plain launch
    pdl_launch(k_scan, NB_SCAN, 1024);
    pdl_launch(k_scatter, NB_E8, 256, src, dst);

    const int GEMM_BLOCKS = (NN + 127) / 128;  // 782
    const int AGG_BLOCKS  = NN / 8;            // 12500

    // layer 1
    pdl_launch(k_gemm_wmma<true >, GEMM_BLOCKS, 256, (const void*)x, Wt[0], p_h);
    pdl_launch(k_agg<true >, AGG_BLOCKS, 256, (const __half2*)p_h, bt[0], (void*)p_a);
    // layer 2
    pdl_launch(k_gemm_wmma<false>, GEMM_BLOCKS, 256, (const void*)p_a, Wt[1], p_h);
    pdl_launch(k_agg<true >, AGG_BLOCKS, 256, (const __half2*)p_h, bt[1], (void*)p_b);
    // layer 3
    pdl_launch(k_gemm_wmma<false>, GEMM_BLOCKS, 256, (const void*)p_b, Wt[2], p_h);
    pdl_launch(k_agg<true >, AGG_BLOCKS, 256, (const __half2*)p_h, bt[2], (void*)p_a);
    // layer 4
    pdl_launch(k_gemm_wmma<false>, GEMM_BLOCKS, 256, (const void*)p_a, Wt[3], p_h);
    pdl_launch(k_agg<false>, AGG_BLOCKS, 256, (const __half2*)p_h, bt[3], d_out);
}

// round 17
// speedup vs baseline: 1.3339x; 1.0012x over previous
#include <cuda_runtime.h>
#include <cuda_fp16.h>
#include <mma.h>
#include <math.h>
#include <stdint.h>

using namespace nvcuda;

#define NN 100000
#define EE 1600000
#define NEG 0.01f
#define COLCAP 2000000   // EE + 3*NN padding worst case, rounded up
#define ASTRIDE 72       // padded smem row stride in halves (144 B = 36 banks)
#define CSTRIDE 20       // padded epilogue staging stride in floats (80 B)

// ---------------- scratch (device globals) ---------------------------------
__device__ __half2 g_h[(NN + 1) * 32];   // row NN stays zero forever (pad target)
__device__ __half2 g_bufA[NN * 32];
__device__ __half2 g_bufB[NN * 32];
__device__ int   g_cnt[NN];              // ==0 at entry (module init / k_scan restores)
__device__ int2  g_rowcnt[NN];           // {rowptr, cnt} packed, one LDG.64
__device__ int   g_pos[NN];
__device__ int   g_col[COLCAP];
__device__ float g_dinv[NN];
__device__ int   g_total;                // ==0 at entry (module init / k_scatter restores)

// ---------------- CSR build ------------------------------------------------
__global__ void k_hist(const int* __restrict__ dst) {
    cudaGridDependencySynchronize();
    int t = blockIdx.x * blockDim.x + threadIdx.x;
    if (t * 8 < EE) {
        int4 d0 = ((const int4*)dst)[t * 2];
        int4 d1 = ((const int4*)dst)[t * 2 + 1];
        atomicAdd(&g_cnt[d0.x], 1);
        atomicAdd(&g_cnt[d0.y], 1);
        atomicAdd(&g_cnt[d0.z], 1);
        atomicAdd(&g_cnt[d0.w], 1);
        atomicAdd(&g_cnt[d1.x], 1);
        atomicAdd(&g_cnt[d1.y], 1);
        atomicAdd(&g_cnt[d1.z], 1);
        atomicAdd(&g_cnt[d1.w], 1);
    }
}

// Fused scan: per-block padded prefix + atomic block-offset grab + rowcnt/pos
// finalize + pad fill + dinv + g_cnt re-zero.
__global__ void k_scan() {
    __shared__ int s[1024];
    __shared__ int sbase;
    cudaGridDependencySynchronize();
    int tid = threadIdx.x;
    int i = blockIdx.x * 1024 + tid;
    int v = (i < NN) ? g_cnt[i] : 0;
    if (i < NN) {
        g_dinv[i] = rsqrtf((float)(v + 1));
        g_cnt[i] = 0;                      // restore invariant for next replay
    }
    int vp = (v + 3) & ~3;                 // padded count
    s[tid] = vp;
    __syncthreads();
    #pragma unroll
    for (int off = 1; off < 1024; off <<= 1) {
        int t = (tid >= off) ? s[tid - off] : 0;
        __syncthreads();
        s[tid] += t;
        __syncthreads();
    }
    if (tid == 1023) sbase = atomicAdd(&g_total, s[1023]);
    __syncthreads();
    if (i < NN) {
        int rp = sbase + s[tid] - vp;      // exclusive padded prefix
        g_rowcnt[i] = make_int2(rp, v);
        g_pos[i] = rp;
        for (int k = v; k < vp; k++) g_col[rp + k] = NN;  // dummy -> zero row
    }
}

__global__ void k_scatter(const int* __restrict__ src, const int* __restrict__ dst) {
    cudaGridDependencySynchronize();
    int t = blockIdx.x * blockDim.x + threadIdx.x;
    if (t == 0) g_total = 0;               // reset cursor for next replay
    if (t * 8 < EE) {
        int4 d0 = ((const int4*)dst)[t * 2];
        int4 d1 = ((const int4*)dst)[t * 2 + 1];
        int4 s0 = ((const int4*)src)[t * 2];
        int4 s1 = ((const int4*)src)[t * 2 + 1];
        int p0 = atomicAdd(&g_pos[d0.x], 1);
        int p1 = atomicAdd(&g_pos[d0.y], 1);
        int p2 = atomicAdd(&g_pos[d0.z], 1);
        int p3 = atomicAdd(&g_pos[d0.w], 1);
        int p4 = atomicAdd(&g_pos[d1.x], 1);
        int p5 = atomicAdd(&g_pos[d1.y], 1);
        int p6 = atomicAdd(&g_pos[d1.z], 1);
        int p7 = atomicAdd(&g_pos[d1.w], 1);
        g_col[p0] = s0.x;
        g_col[p1] = s0.y;
        g_col[p2] = s0.z;
        g_col[p3] = s0.w;
        g_col[p4] = s1.x;
        g_col[p5] = s1.y;
        g_col[p6] = s1.z;
        g_col[p7] = s1.w;
    }
}

// ---------------- WMMA GEMM: h'[N,64](fp16) = dinv[row]*(in @ W) -----------
// ASTRIDE pad kills the operand-load conflicts (R16: 29 -> 17 us);
// CSTRIDE pad kills the epilogue-staging conflicts (8-way -> 2-way).
template<bool F32IN>
__global__ void __launch_bounds__(256) k_gemm_wmma(
    const void* __restrict__ inv, const float* __restrict__ W,
    __half2* __restrict__ out) {
    __shared__ __align__(16) char sraw[(128 + 64) * ASTRIDE * 2 + 256];
    half* As = (half*)sraw;                              // 128 x 72 halves
    half* Bs = (half*)sraw + 128 * ASTRIDE;              // 64 x 72 halves
    int tid  = threadIdx.x;
    int warp = tid >> 5, lane = tid & 31;
    int rowbase = blockIdx.x * 128;

    #pragma unroll
    for (int k = 0; k < 4; k++) {
        int i = tid + k * 256;               // 1024 float4 = W
        int r = i >> 4, c = i & 15;          // row r, cols 4c..4c+3
        float4 w = ((const float4*)W)[i];
        __half2 h0 = __floats2half2_rn(w.x, w.y);
        __half2 h1 = __floats2half2_rn(w.z, w.w);
        *(uint2*)(Bs + r * ASTRIDE + c * 4) =
            make_uint2(*(uint32_t*)&h0, *(uint32_t*)&h1);
    }
    cudaGridDependencySynchronize();
    if (F32IN) {
        const float4* in4 = (const float4*)inv;
        #pragma unroll
        for (int k = 0; k < 8; k++) {
            int i = tid + k * 256;
            int row = i >> 4, q = i & 15;
            int gr = rowbase + row;
            float4 v = (gr < NN) ? in4[(size_t)gr * 16 + q] : make_float4(0, 0, 0, 0);
            __half2 h0 = __floats2half2_rn(v.x, v.y);
            __half2 h1 = __floats2half2_rn(v.z, v.w);
            *(uint2*)(As + row * ASTRIDE + q * 4) =
                make_uint2(*(uint32_t*)&h0, *(uint32_t*)&h1);
        }
    } else {
        const uint4* in4 = (const uint4*)inv;
        #pragma unroll
        for (int k = 0; k < 4; k++) {
            int i = tid + k * 256;
            int row = i >> 3, q = i & 7;
            int gr = rowbase + row;
            uint4 v = (gr < NN) ? in4[(size_t)gr * 8 + q] : make_uint4(0, 0, 0, 0);
            *(uint4*)(As + row * ASTRIDE + q * 8) = v;   // 144B row: 16B aligned
        }
    }
    __syncthreads();

    wmma::fragment<wmma::accumulator, 16, 16, 16, float> c[4];
    #pragma unroll
    for (int nt = 0; nt < 4; nt++) wmma::fill_fragment(c[nt], 0.0f);
    const half* arow = As + warp * 16 * ASTRIDE;
    #pragma unroll
    for (int k0 = 0; k0 < 64; k0 += 16) {
        wmma::fragment<wmma::matrix_a, 16, 16, 16, half, wmma::row_major> a;
        wmma::load_matrix_sync(a, arow + k0, ASTRIDE);
        #pragma unroll
        for (int nt = 0; nt < 4; nt++) {
            wmma::fragment<wmma::matrix_b, 16, 16, 16, half, wmma::row_major> b;
            wmma::load_matrix_sync(b, Bs + k0 * ASTRIDE + nt * 16, ASTRIDE);
            wmma::mma_sync(c[nt], a, b, c[nt]);
        }
    }
    __syncthreads();

    // epilogue: staging tile with CSTRIDE=20 float rows (conflict-padded)
    float* Cst = (float*)sraw + warp * (16 * CSTRIDE);
    int r = lane >> 1;
    int chalf = (lane & 1) * 8;
    int grow = rowbase + warp * 16 + r;
    float di = (grow < NN) ? g_dinv[grow] : 0.f;
    #pragma unroll
    for (int nt = 0; nt < 4; nt++) {
        wmma::store_matrix_sync(Cst, c[nt], CSTRIDE, wmma::mem_row_major);
        __syncwarp();
        if (grow < NN) {
            float4 v0 = *(const float4*)(Cst + r * CSTRIDE + chalf);
            float4 v1 = *(const float4*)(Cst + r * CSTRIDE + chalf + 4);
            __half2 h0 = __floats2half2_rn(di * v0.x, di * v0.y);
            __half2 h1 = __floats2half2_rn(di * v0.z, di * v0.w);
            __half2 h2 = __floats2half2_rn(di * v1.x, di * v1.y);
            __half2 h3 = __floats2half2_rn(di * v1.z, di * v1.w);
            *(uint4*)(out + (size_t)grow * 32 + nt * 8 + (lane & 1) * 4) =
                make_uint4(*(uint32_t*)&h0, *(uint32_t*)&h1,
                           *(uint32_t*)&h2, *(uint32_t*)&h3);
        }
        __syncwarp();
    }
}

// ---------------- Aggregation: warp-per-row, 16-wide gather batches --------
template<bool HALF_OUT>
__global__ void k_agg(const __half2* __restrict__ h, const float* __restrict__ bias,
                      void* __restrict__ outv) {
    int wid  = (blockIdx.x * blockDim.x + threadIdx.x) >> 5;
    int lane = threadIdx.x & 31;
    float2 bb = ((const float2*)bias)[lane];   // input tensor: safe pre-sync
    cudaGridDependencySynchronize();
    if (wid >= NN) return;
    int2 rc   = g_rowcnt[wid];
    int start = rc.x, cnt = rc.y;
    float di  = g_dinv[wid];
    const int* cp = g_col + start;
    int cntp = (cnt + 3) & ~3;

    float a0 = 0.f, a1 = 0.f;
    int j = 0;
    for (; j + 16 <= cntp; j += 16) {
        int4 sa = *(const int4*)(cp + j);
        int4 sb = *(const int4*)(cp + j + 4);
        int4 sc = *(const int4*)(cp + j + 8);
        int4 sd = *(const int4*)(cp + j + 12);
        __half2 v0 = h[sa.x * 32 + lane];
        __half2 v1 = h[sa.y * 32 + lane];
        __half2 v2 = h[sa.z * 32 + lane];
        __half2 v3 = h[sa.w * 32 + lane];
        __half2 v4 = h[sb.x * 32 + lane];
        __half2 v5 = h[sb.y * 32 + lane];
        __half2 v6 = h[sb.z * 32 + lane];
        __half2 v7 = h[sb.w * 32 + lane];
        __half2 v8 = h[sc.x * 32 + lane];
        __half2 v9 = h[sc.y * 32 + lane];
        __half2 va = h[sc.z * 32 + lane];
        __half2 vb = h[sc.w * 32 + lane];
        __half2 vc = h[sd.x * 32 + lane];
        __half2 vd = h[sd.y * 32 + lane];
        __half2 ve = h[sd.z * 32 + lane];
        __half2 vf = h[sd.w * 32 + lane];
        float2 f0 = __half22float2(v0), f1 = __half22float2(v1);
        float2 f2 = __half22float2(v2), f3 = __half22float2(v3);
        float2 f4 = __half22float2(v4), f5 = __half22float2(v5);
        float2 f6 = __half22float2(v6), f7 = __half22float2(v7);
        float2 f8 = __half22float2(v8), f9 = __half22float2(v9);
        float2 fa = __half22float2(va), fb = __half22float2(vb);
        float2 fc = __half22float2(vc), fd = __half22float2(vd);
        float2 fe = __half22float2(ve), ff = __half22float2(vf);
        a0 += f0.x + f1.x + f2.x + f3.x + f4.x + f5.x + f6.x + f7.x
            + f8.x + f9.x + fa.x + fb.x + fc.x + fd.x + fe.x + ff.x;
        a1 += f0.y + f1.y + f2.y + f3.y + f4.y + f5.y + f6.y + f7.y
            + f8.y + f9.y + fa.y + fb.y + fc.y + fd.y + fe.y + ff.y;
    }
    if (j + 8 <= cntp) {
        int4 sa = *(const int4*)(cp + j);
        int4 sb = *(const int4*)(cp + j + 4);
        __half2 v0 = h[sa.x * 32 + lane];
        __half2 v1 = h[sa.y * 32 + lane];
        __half2 v2 = h[sa.z * 32 + lane];
        __half2 v3 = h[sa.w * 32 + lane];
        __half2 v4 = h[sb.x * 32 + lane];
        __half2 v5 = h[sb.y * 32 + lane];
        __half2 v6 = h[sb.z * 32 + lane];
        __half2 v7 = h[sb.w * 32 + lane];
        float2 f0 = __half22float2(v0), f1 = __half22float2(v1);
        float2 f2 = __half22float2(v2), f3 = __half22float2(v3);
        float2 f4 = __half22float2(v4), f5 = __half22float2(v5);
        float2 f6 = __half22float2(v6), f7 = __half22float2(v7);
        a0 += f0.x + f1.x + f2.x + f3.x + f4.x + f5.x + f6.x + f7.x;
        a1 += f0.y + f1.y + f2.y + f3.y + f4.y + f5.y + f6.y + f7.y;
        j += 8;
    }
    if (j < cntp) {
        int4 sa = *(const int4*)(cp + j);
        __half2 v0 = h[sa.x * 32 + lane];
        __half2 v1 = h[sa.y * 32 + lane];
        __half2 v2 = h[sa.z * 32 + lane];
        __half2 v3 = h[sa.w * 32 + lane];
        float2 f0 = __half22float2(v0), f1 = __half22float2(v1);
        float2 f2 = __half22float2(v2), f3 = __half22float2(v3);
        a0 += f0.x + f1.x + f2.x + f3.x;
        a1 += f0.y + f1.y + f2.y + f3.y;
    }

    float2 hs = __half22float2(h[wid * 32 + lane]);
    float o0 = di * (a0 + hs.x) + bb.x;
    float o1 = di * (a1 + hs.y) + bb.y;
    o0 = (o0 >= 0.f) ? o0 : NEG * o0;
    o1 = (o1 >= 0.f) ? o1 : NEG * o1;
    if (HALF_OUT) {
        ((__half2*)outv)[(size_t)wid * 32 + lane] = __floats2half2_rn(o0, o1);
    } else {
        float2 oo; oo.x = o0; oo.y = o1;
        ((float2*)outv)[(size_t)wid * 32 + lane] = oo;
    }
}

// ---------------- launch (PDL-chained) --------------------------------------
template<typename K, typename... Args>
static inline void pdl_launch(K kern, int grid, int block, Args... args) {
    cudaLaunchConfig_t cfg = {};
    cfg.gridDim = dim3(grid);
    cfg.blockDim = dim3(block);
    cudaLaunchAttribute attr[1];
    attr[0].id = cudaLaunchAttributeProgrammaticStreamSerialization;
    attr[0].val.programmaticStreamSerializationAllowed = 1;
    cfg.attrs = attr;
    cfg.numAttrs = 1;
    cudaLaunchKernelEx(&cfg, kern, args...);
}

extern "C" void kernel_launch(void* const* d_in, const int* in_sizes, int n_in,
                              void* d_out, int out_size) {
    (void)in_sizes; (void)n_in; (void)out_size;
    const float* x  = (const float*)d_in[0];
    const int*   ei = (const int*)d_in[1];
    const int* src = ei;
    const int* dst = ei + EE;
    const float* Wt[4] = { (const float*)d_in[2], (const float*)d_in[4],
                           (const float*)d_in[6], (const float*)d_in[8] };
    const float* bt[4] = { (const float*)d_in[3], (const float*)d_in[5],
                           (const float*)d_in[7], (const float*)d_in[9] };

    __half2 *p_h, *p_a, *p_b;
    cudaGetSymbolAddress((void**)&p_h, g_h);
    cudaGetSymbolAddress((void**)&p_a, g_bufA);
    cudaGetSymbolAddress((void**)&p_b, g_bufB);

    const int NB_SCAN = (NN + 1023) / 1024;    // 98
    const int NB_E8   = (EE / 8 + 255) / 256;  // 782

    // CSR build — g_cnt==0 and g_total==0 at entry (module init / restored)
    k_hist<<<NB_E8, 256>>>(dst);               // head of chain: plain launch
    pdl_launch(k_scan, NB_SCAN, 1024);
    pdl_launch(k_scatter, NB_E8, 256, src, dst);

    const int GEMM_BLOCKS = (NN + 127) / 128;  // 782
    const int AGG_BLOCKS  = NN / 8;            // 12500

    // layer 1
    pdl_launch(k_gemm_wmma<true >, GEMM_BLOCKS, 256, (const void*)x, Wt[0], p_h);
    pdl_launch(k_agg<true >, AGG_BLOCKS, 256, (const __half2*)p_h, bt[0], (void*)p_a);
    // layer 2
    pdl_launch(k_gemm_wmma<false>, GEMM_BLOCKS, 256, (const void*)p_a, Wt[1], p_h);
    pdl_launch(k_agg<true >, AGG_BLOCKS, 256, (const __half2*)p_h, bt[1], (void*)p_b);
    // layer 3
    pdl_launch(k_gemm_wmma<false>, GEMM_BLOCKS, 256, (const void*)p_b, Wt[2], p_h);
    pdl_launch(k_agg<true >, AGG_BLOCKS, 256, (const __half2*)p_h, bt[2], (void*)p_a);
    // layer 4
    pdl_launch(k_gemm_wmma<false>, GEMM_BLOCKS, 256, (const void*)p_a, Wt[3], p_h);
    pdl_launch(k_agg<false>, AGG_BLOCKS, 256, (const __half2*)p_h, bt[3], d_out);
}